// round 13
// baseline (speedup 1.0000x reference)
#include <cuda_runtime.h>
#include <cuda_bf16.h>
#include <math.h>
#include <stdint.h>

// ===========================================================================
// MoE layer via mma.sync bf16 split-precision (fused 3-term) GEMMs.
// R13: occupancy is the proven lever (R12: 2 CTAs/SM -> tensor 68%). Push to
//   3 CTAs/SM of the same 256-thread shape: KCH 64->32 (64B rows, SW64
//   swizzle), stage 24KB, STAGES=3 -> 72KB/CTA, launch_bounds(256,3).
//   Warp tiling / MMA:LDSM ratio / accumulation order unchanged (rel_err
//   must stay exactly 2.66469e-5 -- acts as a swizzle-correctness check).
//   Also fixed: tail iterations use cp_wait<0> (empty commit groups can
//   satisfy cp_wait<1> without the last real chunk being complete).
// ===========================================================================

#define NTOK  8192
#define DIM   2048
#define NEXP  8

// -------- GEMM tiling --------
#define TILE_M 128
#define TILE_N 64
#define KCH    32                       // bf16 elems per K-chunk (=64B row)
#define NCHUNK (DIM / KCH)              // 64 fused chunks
#define STAGES 3
#define ROWB   64                       // bytes per tile row
#define A_T_BYTES (TILE_M * ROWB)       // 8 KB per A tile
#define B_T_BYTES (TILE_N * ROWB)       // 4 KB per B tile
#define STAGE_BYTES (2 * A_T_BYTES + 2 * B_T_BYTES)  // 24 KB
#define GTHREADS 256                    // 8 warps: 4x2 grid, 32x32 warp tiles
#define GEMM_DYN_SMEM (STAGES * STAGE_BYTES)  // 72 KB -> 3 CTAs/SM

// -------- scratch (static device globals; runtime alloc is forbidden) ------
__device__ __nv_bfloat16 g_xh[(size_t)NTOK * DIM];   // x hi   (reused as act2 hi)
__device__ __nv_bfloat16 g_xl[(size_t)NTOK * DIM];   // x lo   (reused as act2 lo)
__device__ __nv_bfloat16 g_t1h[(size_t)NTOK * DIM];  // act1 hi
__device__ __nv_bfloat16 g_t1l[(size_t)NTOK * DIM];  // act1 lo
__device__ __nv_bfloat16 g_w1h[(size_t)DIM * DIM];
__device__ __nv_bfloat16 g_w1l[(size_t)DIM * DIM];
__device__ __nv_bfloat16 g_w3h[(size_t)DIM * DIM];
__device__ __nv_bfloat16 g_w3l[(size_t)DIM * DIM];
__device__ __nv_bfloat16 g_w2h[(size_t)DIM * DIM];
__device__ __nv_bfloat16 g_w2l[(size_t)DIM * DIM];
__device__ float g_h[(size_t)NTOK * DIM];            // final FFN output fp32
__device__ float g_C[(size_t)NTOK * NEXP];           // routing coefficients
__device__ float g_part[(size_t)(NTOK / 128) * NEXP * DIM];

// ===========================================================================
// helpers
// ===========================================================================
__device__ __forceinline__ uint32_t smem_u32(const void* p) {
    uint32_t a;
    asm("{ .reg .u64 t; cvta.to.shared.u64 t, %1; cvt.u32.u64 %0, t; }"
        : "=r"(a) : "l"(p));
    return a;
}
#define SWZ64(off) ((off) ^ (((off) >> 3) & 0x30))

__device__ __forceinline__ void cp_async16(uint32_t dst, const void* src) {
    asm volatile("cp.async.cg.shared.global [%0], [%1], 16;"
                 :: "r"(dst), "l"(src) : "memory");
}
__device__ __forceinline__ void cp_commit() {
    asm volatile("cp.async.commit_group;" ::: "memory");
}
template <int N>
__device__ __forceinline__ void cp_wait() {
    asm volatile("cp.async.wait_group %0;" :: "n"(N) : "memory");
}
__device__ __forceinline__ void ldmatrix_x4(uint32_t& r0, uint32_t& r1,
                                            uint32_t& r2, uint32_t& r3,
                                            uint32_t addr) {
    asm volatile("ldmatrix.sync.aligned.m8n8.x4.shared.b16 {%0,%1,%2,%3}, [%4];"
                 : "=r"(r0), "=r"(r1), "=r"(r2), "=r"(r3) : "r"(addr));
}
__device__ __forceinline__ void mma16816(float& d0, float& d1, float& d2, float& d3,
                                         uint32_t a0, uint32_t a1, uint32_t a2, uint32_t a3,
                                         uint32_t b0, uint32_t b1) {
    asm volatile(
        "mma.sync.aligned.m16n8k16.row.col.f32.bf16.bf16.f32 "
        "{%0,%1,%2,%3}, {%4,%5,%6,%7}, {%8,%9}, {%0,%1,%2,%3};"
        : "+f"(d0), "+f"(d1), "+f"(d2), "+f"(d3)
        : "r"(a0), "r"(a1), "r"(a2), "r"(a3), "r"(b0), "r"(b1));
}

// ===========================================================================
// fused split-precision GEMM:  C[M,N] = A[M,K] * B[N,K]^T (fp32 via bf16)
//   per k-chunk (K=32) computes Ah*Bh + Al*Bh + Ah*Bl from one staging.
//   mode 0: epilogue silu -> split into (OutH, OutL) bf16
//   mode 1: epilogue raw fp32 -> OutF
// 8 warps as 4 (rows, 32 each) x 2 (cols, 32 each).
// ===========================================================================
__global__ void __launch_bounds__(GTHREADS, 3)
gemm_bf16x3(const __nv_bfloat16* __restrict__ Ah,
            const __nv_bfloat16* __restrict__ Al,
            const __nv_bfloat16* __restrict__ Bh,
            const __nv_bfloat16* __restrict__ Bl,
            __nv_bfloat16* __restrict__ OutH,
            __nv_bfloat16* __restrict__ OutL,
            float* __restrict__ OutF,
            int mode) {
    extern __shared__ char dynsm[];
    const uint32_t sm_base = smem_u32(dynsm);

    const int tid    = threadIdx.x;
    const int wid    = tid >> 5;
    const int lane   = tid & 31;
    const int warp_m = wid & 3;    // 4 row-warps: 32 rows each
    const int warp_n = wid >> 2;   // 2 col-warps: 32 cols each
    const int bm = blockIdx.y * TILE_M;
    const int bn = blockIdx.x * TILE_N;

    // fp32 accumulators: 2 m16-tiles x 4 n8-tiles x 4 regs = 32
    float acc[2][4][4];
#pragma unroll
    for (int i = 0; i < 2; i++)
#pragma unroll
        for (int j = 0; j < 4; j++)
#pragma unroll
            for (int r = 0; r < 4; r++) acc[i][j][r] = 0.f;

    // ldmatrix per-lane byte offsets within a 64B-row tile (pre-swizzle)
    uint32_t a_off[2], b_off[2];
#pragma unroll
    for (int mi = 0; mi < 2; mi++) {
        const int row = warp_m * 32 + mi * 16 + (lane & 15);
        a_off[mi] = row * ROWB + (lane >> 4) * 16;
    }
#pragma unroll
    for (int g = 0; g < 2; g++) {
        const int row = warp_n * 32 + g * 16 + (lane & 15);
        b_off[g] = row * ROWB + (lane >> 4) * 16;
    }

    // cp.async per chunk: A tiles 512 vecs each (2/thread), B tiles 256 (1/thread)
    auto issue_chunk = [&](int c) {
        const int k0 = c * KCH;
        const uint32_t stage = sm_base + (uint32_t)(c % STAGES) * STAGE_BYTES;
        const __nv_bfloat16* Asrcs[2] = { Ah + (size_t)bm * DIM + k0,
                                          Al + (size_t)bm * DIM + k0 };
        const __nv_bfloat16* Bsrcs[2] = { Bh + (size_t)bn * DIM + k0,
                                          Bl + (size_t)bn * DIM + k0 };
#pragma unroll
        for (int t = 0; t < 2; t++) {
#pragma unroll
            for (int i = 0; i < 2; i++) {
                const int f = tid + i * 256;
                const int r = f >> 2, v = f & 3;     // 4 x 16B per 64B row
                cp_async16(stage + (uint32_t)t * A_T_BYTES + SWZ64(r * ROWB + v * 16),
                           Asrcs[t] + (size_t)r * DIM + v * 8);
            }
        }
#pragma unroll
        for (int t = 0; t < 2; t++) {
            const int r = tid >> 2, v = tid & 3;
            cp_async16(stage + 2 * A_T_BYTES + (uint32_t)t * B_T_BYTES
                           + SWZ64(r * ROWB + v * 16),
                       Bsrcs[t] + (size_t)r * DIM + v * 8);
        }
    };

    // prologue: chunks 0..STAGES-2
#pragma unroll
    for (int c = 0; c < STAGES - 1; c++) { issue_chunk(c); cp_commit(); }

    for (int c = 0; c < NCHUNK; c++) {
        // Tail guard: once no more real groups are committed, empty groups
        // complete instantly and wait<1> could pass before chunk c lands.
        if (c < NCHUNK - (STAGES - 1)) cp_wait<STAGES - 2>();
        else                           cp_wait<0>();
        __syncthreads();         // publish all copies; compute(c-1) fully done

        // overlap next chunk's global loads with this chunk's compute
        const int nc = c + STAGES - 1;
        if (nc < NCHUNK) issue_chunk(nc);
        cp_commit();             // one group per iteration (possibly empty)

        const uint32_t sAh = sm_base + (uint32_t)(c % STAGES) * STAGE_BYTES;
        const uint32_t sAl = sAh + A_T_BYTES;
        const uint32_t sBh = sAh + 2 * A_T_BYTES;
        const uint32_t sBl = sBh + B_T_BYTES;
#pragma unroll
        for (int k16 = 0; k16 < 2; k16++) {
            const uint32_t kb = k16 * 32;
            uint32_t ah[2][4], al[2][4], bh[2][4], bl[2][4];
#pragma unroll
            for (int mi = 0; mi < 2; mi++) {
                ldmatrix_x4(ah[mi][0], ah[mi][1], ah[mi][2], ah[mi][3],
                            sAh + SWZ64(a_off[mi] + kb));
                ldmatrix_x4(al[mi][0], al[mi][1], al[mi][2], al[mi][3],
                            sAl + SWZ64(a_off[mi] + kb));
            }
#pragma unroll
            for (int g = 0; g < 2; g++) {
                ldmatrix_x4(bh[g][0], bh[g][1], bh[g][2], bh[g][3],
                            sBh + SWZ64(b_off[g] + kb));
                ldmatrix_x4(bl[g][0], bl[g][1], bl[g][2], bl[g][3],
                            sBl + SWZ64(b_off[g] + kb));
            }
            // terms: Ah*Bh, Al*Bh, Ah*Bl (fragments reused from registers)
#pragma unroll
            for (int mi = 0; mi < 2; mi++)
#pragma unroll
                for (int g = 0; g < 2; g++) {
                    mma16816(acc[mi][2*g][0], acc[mi][2*g][1],
                             acc[mi][2*g][2], acc[mi][2*g][3],
                             ah[mi][0], ah[mi][1], ah[mi][2], ah[mi][3],
                             bh[g][0], bh[g][2]);
                    mma16816(acc[mi][2*g+1][0], acc[mi][2*g+1][1],
                             acc[mi][2*g+1][2], acc[mi][2*g+1][3],
                             ah[mi][0], ah[mi][1], ah[mi][2], ah[mi][3],
                             bh[g][1], bh[g][3]);
                    mma16816(acc[mi][2*g][0], acc[mi][2*g][1],
                             acc[mi][2*g][2], acc[mi][2*g][3],
                             al[mi][0], al[mi][1], al[mi][2], al[mi][3],
                             bh[g][0], bh[g][2]);
                    mma16816(acc[mi][2*g+1][0], acc[mi][2*g+1][1],
                             acc[mi][2*g+1][2], acc[mi][2*g+1][3],
                             al[mi][0], al[mi][1], al[mi][2], al[mi][3],
                             bh[g][1], bh[g][3]);
                    mma16816(acc[mi][2*g][0], acc[mi][2*g][1],
                             acc[mi][2*g][2], acc[mi][2*g][3],
                             ah[mi][0], ah[mi][1], ah[mi][2], ah[mi][3],
                             bl[g][0], bl[g][2]);
                    mma16816(acc[mi][2*g+1][0], acc[mi][2*g+1][1],
                             acc[mi][2*g+1][2], acc[mi][2*g+1][3],
                             ah[mi][0], ah[mi][1], ah[mi][2], ah[mi][3],
                             bl[g][1], bl[g][3]);
                }
        }
    }

    // ---- epilogue ----
#pragma unroll
    for (int mi = 0; mi < 2; mi++) {
        const int row0 = bm + warp_m * 32 + mi * 16 + (lane >> 2);
#pragma unroll
        for (int ni = 0; ni < 4; ni++) {
            const int col = bn + warp_n * 32 + ni * 8 + (lane & 3) * 2;
#pragma unroll
            for (int half = 0; half < 2; half++) {
                const int row = row0 + half * 8;
                const size_t idx = (size_t)row * DIM + col;
                float v0 = acc[mi][ni][half * 2 + 0];
                float v1 = acc[mi][ni][half * 2 + 1];
                if (mode == 0) {
                    v0 = v0 / (1.f + expf(-v0));
                    v1 = v1 / (1.f + expf(-v1));
                    __nv_bfloat16 h0 = __float2bfloat16(v0);
                    __nv_bfloat16 h1 = __float2bfloat16(v1);
                    __nv_bfloat16 l0 = __float2bfloat16(v0 - __bfloat162float(h0));
                    __nv_bfloat16 l1 = __float2bfloat16(v1 - __bfloat162float(h1));
                    *(__nv_bfloat162*)(OutH + idx) = __halves2bfloat162(h0, h1);
                    *(__nv_bfloat162*)(OutL + idx) = __halves2bfloat162(l0, l1);
                } else {
                    *(float2*)(OutF + idx) = make_float2(v0, v1);
                }
            }
        }
    }
}

// ===========================================================================
// fp32 -> (hi, lo) bf16 split; 4 tensors in ONE launch (keeps gemm3 at ncu's
// -s 5 slot). Segments: [0,n0) x, [n0,n0+n1) w1, then w3, w2.
// ===========================================================================
__global__ void split4_kernel(const float4* __restrict__ i0, __nv_bfloat162* __restrict__ h0, __nv_bfloat162* __restrict__ l0, int n0,
                              const float4* __restrict__ i1, __nv_bfloat162* __restrict__ h1, __nv_bfloat162* __restrict__ l1, int n1,
                              const float4* __restrict__ i2, __nv_bfloat162* __restrict__ h2, __nv_bfloat162* __restrict__ l2, int n2,
                              const float4* __restrict__ i3, __nv_bfloat162* __restrict__ h3, __nv_bfloat162* __restrict__ l3, int n3) {
    const int total = n0 + n1 + n2 + n3;
    int i = blockIdx.x * blockDim.x + threadIdx.x;
    const int stride = gridDim.x * blockDim.x;
    for (; i < total; i += stride) {
        const float4* in; __nv_bfloat162* hi; __nv_bfloat162* lo; int j = i;
        if (j < n0)                { in = i0; hi = h0; lo = l0; }
        else if ((j -= n0) < n1)   { in = i1; hi = h1; lo = l1; }
        else if ((j -= n1) < n2)   { in = i2; hi = h2; lo = l2; }
        else { j -= n2;              in = i3; hi = h3; lo = l3; }
        float4 v = in[j];
        __nv_bfloat16 a0 = __float2bfloat16(v.x), a1 = __float2bfloat16(v.y);
        __nv_bfloat16 a2 = __float2bfloat16(v.z), a3 = __float2bfloat16(v.w);
        __nv_bfloat16 b0 = __float2bfloat16(v.x - __bfloat162float(a0));
        __nv_bfloat16 b1 = __float2bfloat16(v.y - __bfloat162float(a1));
        __nv_bfloat16 b2 = __float2bfloat16(v.z - __bfloat162float(a2));
        __nv_bfloat16 b3 = __float2bfloat16(v.w - __bfloat162float(a3));
        hi[2 * j]     = __halves2bfloat162(a0, a1);
        hi[2 * j + 1] = __halves2bfloat162(a2, a3);
        lo[2 * j]     = __halves2bfloat162(b0, b1);
        lo[2 * j + 1] = __halves2bfloat162(b2, b3);
    }
}

// ===========================================================================
// zero-fill output
// ===========================================================================
__global__ void zero_kernel(float4* __restrict__ out, size_t n4) {
    size_t i = (size_t)blockIdx.x * blockDim.x + threadIdx.x;
    size_t stride = (size_t)gridDim.x * blockDim.x;
    float4 z = make_float4(0.f, 0.f, 0.f, 0.f);
    for (; i < n4; i += stride) out[i] = z;
}

// ===========================================================================
// routing: one warp per token; softmax -> top2 -> normalized gates
// ===========================================================================
__global__ void routing_kernel(const float* __restrict__ x,
                               const float* __restrict__ wr,
                               float* __restrict__ C) {
    int gwarp = (blockIdx.x * blockDim.x + threadIdx.x) >> 5;
    int lane  = threadIdx.x & 31;
    if (gwarp >= NTOK) return;
    const float* xr = x + (size_t)gwarp * DIM;
    float acc[NEXP];
#pragma unroll
    for (int e = 0; e < NEXP; e++) acc[e] = 0.f;
    for (int k = lane; k < DIM; k += 32) {
        float xv = xr[k];
#pragma unroll
        for (int e = 0; e < NEXP; e++)
            acc[e] = fmaf(xv, wr[e * DIM + k], acc[e]);
    }
#pragma unroll
    for (int e = 0; e < NEXP; e++) {
#pragma unroll
        for (int off = 16; off > 0; off >>= 1)
            acc[e] += __shfl_xor_sync(0xffffffffu, acc[e], off);
    }
    if (lane == 0) {
        float m = acc[0];
#pragma unroll
        for (int e = 1; e < NEXP; e++) m = fmaxf(m, acc[e]);
        float p[NEXP];
#pragma unroll
        for (int e = 0; e < NEXP; e++) p[e] = expf(acc[e] - m);
        int e0 = 0; float p0 = p[0];
#pragma unroll
        for (int e = 1; e < NEXP; e++) if (p[e] > p0) { p0 = p[e]; e0 = e; }
        int e1 = -1; float p1 = -1.f;
#pragma unroll
        for (int e = 0; e < NEXP; e++)
            if (e != e0 && p[e] > p1) { p1 = p[e]; e1 = e; }
        float inv = 1.f / (p0 + p1);
        float* Cn = C + (size_t)gwarp * NEXP;
#pragma unroll
        for (int e = 0; e < NEXP; e++) {
            float v = 0.f;
            if (e == e0) v = p0 * inv;
            else if (e == e1) v = p1 * inv;
            Cn[e] = v;
        }
    }
}

// ===========================================================================
// expert-weighted reduction (two-stage, deterministic)
// ===========================================================================
__global__ void reduce_partial_kernel(const float* __restrict__ h,
                                      const float* __restrict__ C,
                                      float* __restrict__ part) {
    const int col = blockIdx.x * 128 + threadIdx.x;
    const int n0 = blockIdx.y * 128;
    float acc[NEXP];
#pragma unroll
    for (int e = 0; e < NEXP; e++) acc[e] = 0.f;
    for (int i = 0; i < 128; i++) {
        const int n = n0 + i;
        const float hv = h[(size_t)n * DIM + col];
        const float* Cn = C + (size_t)n * NEXP;
#pragma unroll
        for (int e = 0; e < NEXP; e++)
            acc[e] = fmaf(hv, Cn[e], acc[e]);
    }
#pragma unroll
    for (int e = 0; e < NEXP; e++)
        part[((size_t)blockIdx.y * NEXP + e) * DIM + col] = acc[e];
}

__global__ void reduce_final_kernel(const float* __restrict__ part,
                                    float* __restrict__ out) {
    const int id = blockIdx.x * blockDim.x + threadIdx.x;
    if (id >= NEXP * DIM) return;
    const int e = id / DIM;
    const int col = id % DIM;
    float s = 0.f;
#pragma unroll 4
    for (int by = 0; by < NTOK / 128; by++)
        s += part[((size_t)by * NEXP + e) * DIM + col];
    out[(size_t)e * DIM + col] = s;
}

// ===========================================================================
extern "C" void kernel_launch(void* const* d_in, const int* in_sizes, int n_in,
                              void* d_out, int out_size) {
    const float* x  = (const float*)d_in[0];
    const float* w1 = (const float*)d_in[1];
    const float* w3 = (const float*)d_in[2];
    const float* w2 = (const float*)d_in[3];
    const float* wr = (const float*)d_in[4];
    float* out = (float*)d_out;

    __nv_bfloat16 *xh, *xl, *t1h, *t1l, *w1h, *w1l, *w3h, *w3l, *w2h, *w2l;
    float *hbuf, *C, *part;
    cudaGetSymbolAddress((void**)&xh,  g_xh);
    cudaGetSymbolAddress((void**)&xl,  g_xl);
    cudaGetSymbolAddress((void**)&t1h, g_t1h);
    cudaGetSymbolAddress((void**)&t1l, g_t1l);
    cudaGetSymbolAddress((void**)&w1h, g_w1h);
    cudaGetSymbolAddress((void**)&w1l, g_w1l);
    cudaGetSymbolAddress((void**)&w3h, g_w3h);
    cudaGetSymbolAddress((void**)&w3l, g_w3l);
    cudaGetSymbolAddress((void**)&w2h, g_w2h);
    cudaGetSymbolAddress((void**)&w2l, g_w2l);
    cudaGetSymbolAddress((void**)&hbuf, g_h);
    cudaGetSymbolAddress((void**)&C,    g_C);
    cudaGetSymbolAddress((void**)&part, g_part);

    cudaFuncSetAttribute(gemm_bf16x3,
                         cudaFuncAttributeMaxDynamicSharedMemorySize,
                         GEMM_DYN_SMEM);

    // launch 1: zero output (harness poisons it)
    {
        size_t n4 = (size_t)out_size / 4;
        int blocks = (int)((n4 + 255) / 256);
        if (blocks > 16384) blocks = 16384;
        zero_kernel<<<blocks, 256>>>((float4*)out, n4);
    }

    // launch 2: routing coefficients (fp32, faithful top-k)
    routing_kernel<<<(NTOK * 32) / 256, 256>>>(x, wr, C);

    // launch 3: all hi/lo splits fused
    const int nx4 = NTOK * DIM / 4, nw4 = DIM * DIM / 4;
    split4_kernel<<<2048, 256>>>(
        (const float4*)x,  (__nv_bfloat162*)xh,  (__nv_bfloat162*)xl,  nx4,
        (const float4*)w1, (__nv_bfloat162*)w1h, (__nv_bfloat162*)w1l, nw4,
        (const float4*)w3, (__nv_bfloat162*)w3h, (__nv_bfloat162*)w3l, nw4,
        (const float4*)w2, (__nv_bfloat162*)w2h, (__nv_bfloat162*)w2l, nw4);

    // launches 4-6: FFN chain (ncu -s 5 -c 1 profiles launch 6 = gemm3)
    dim3 ggrid(DIM / TILE_N, NTOK / TILE_M);  // (32, 64)
    gemm_bf16x3<<<ggrid, GTHREADS, GEMM_DYN_SMEM>>>(xh, xl, w1h, w1l,
                                                    t1h, t1l, nullptr, 0);
    gemm_bf16x3<<<ggrid, GTHREADS, GEMM_DYN_SMEM>>>(t1h, t1l, w3h, w3l,
                                                    xh, xl, nullptr, 0);   // reuse x bufs
    gemm_bf16x3<<<ggrid, GTHREADS, GEMM_DYN_SMEM>>>(xh, xl, w2h, w2l,
                                                    nullptr, nullptr, hbuf, 1);

    // launches 7-8: expert-weighted reduction into rows 0..7
    reduce_partial_kernel<<<dim3(DIM / 128, NTOK / 128), 128>>>(hbuf, C, part);
    reduce_final_kernel<<<(NEXP * DIM + 255) / 256, 256>>>(part, out);
}

// round 16
// speedup vs baseline: 1.1329x; 1.1329x over previous
#include <cuda_runtime.h>
#include <cuda_bf16.h>
#include <math.h>
#include <stdint.h>

// ===========================================================================
// MoE layer via mma.sync bf16 split-precision (fused 3-term) GEMMs.
// R16: R14/R15 (full term-outermost MMA hoist) killed the container twice ->
//   that exact restructuring is off-limits (suspected build-side effect; all
//   these failures show zero harness output). This round applies the MINIMAL
//   form of the same RAW-distance fix inside R12's proven structure: the
//   term sequence is hoisted only above the g-loop (within the mi-loop).
//   Same-accumulator MMA distance 2 -> 4 (~17.6cyc >= 10-16cyc acc RAW).
//   Per-accumulator add order unchanged (hh, lh, hl) -> bit-identical.
//   Everything else = R12 exactly (2 CTAs/SM, KCH=64, STAGES=2, 256 thr).
// ===========================================================================

#define NTOK  8192
#define DIM   2048
#define NEXP  8

// -------- GEMM tiling --------
#define TILE_M 128
#define TILE_N 64
#define KCH    64                       // bf16 elems per K-chunk (=128B row)
#define NCHUNK (DIM / KCH)              // 32 fused chunks
#define STAGES 2
#define A_BYTES (TILE_M * 128)          // 16 KB per A tile
#define B_BYTES (TILE_N * 128)          // 8 KB per B tile
#define STAGE_BYTES (2 * A_BYTES + 2 * B_BYTES)  // Ah,Al,Bh,Bl = 48 KB
#define GTHREADS 256                    // 8 warps: 4x2 grid, 32x32 warp tiles
#define GEMM_DYN_SMEM (STAGES * STAGE_BYTES)  // 96 KB -> 2 CTAs/SM

// -------- scratch (static device globals; runtime alloc is forbidden) ------
__device__ __nv_bfloat16 g_xh[(size_t)NTOK * DIM];   // x hi   (reused as act2 hi)
__device__ __nv_bfloat16 g_xl[(size_t)NTOK * DIM];   // x lo   (reused as act2 lo)
__device__ __nv_bfloat16 g_t1h[(size_t)NTOK * DIM];  // act1 hi
__device__ __nv_bfloat16 g_t1l[(size_t)NTOK * DIM];  // act1 lo
__device__ __nv_bfloat16 g_w1h[(size_t)DIM * DIM];
__device__ __nv_bfloat16 g_w1l[(size_t)DIM * DIM];
__device__ __nv_bfloat16 g_w3h[(size_t)DIM * DIM];
__device__ __nv_bfloat16 g_w3l[(size_t)DIM * DIM];
__device__ __nv_bfloat16 g_w2h[(size_t)DIM * DIM];
__device__ __nv_bfloat16 g_w2l[(size_t)DIM * DIM];
__device__ float g_h[(size_t)NTOK * DIM];            // final FFN output fp32
__device__ float g_C[(size_t)NTOK * NEXP];           // routing coefficients
__device__ float g_part[(size_t)(NTOK / 128) * NEXP * DIM];

// ===========================================================================
// helpers
// ===========================================================================
__device__ __forceinline__ uint32_t smem_u32(const void* p) {
    uint32_t a;
    asm("{ .reg .u64 t; cvta.to.shared.u64 t, %1; cvt.u32.u64 %0, t; }"
        : "=r"(a) : "l"(p));
    return a;
}
#define SWZ128(off) ((off) ^ (((off) >> 3) & 0x70))

__device__ __forceinline__ void cp_async16(uint32_t dst, const void* src) {
    asm volatile("cp.async.cg.shared.global [%0], [%1], 16;"
                 :: "r"(dst), "l"(src) : "memory");
}
__device__ __forceinline__ void cp_commit() {
    asm volatile("cp.async.commit_group;" ::: "memory");
}
template <int N>
__device__ __forceinline__ void cp_wait() {
    asm volatile("cp.async.wait_group %0;" :: "n"(N) : "memory");
}
__device__ __forceinline__ void ldmatrix_x4(uint32_t& r0, uint32_t& r1,
                                            uint32_t& r2, uint32_t& r3,
                                            uint32_t addr) {
    asm volatile("ldmatrix.sync.aligned.m8n8.x4.shared.b16 {%0,%1,%2,%3}, [%4];"
                 : "=r"(r0), "=r"(r1), "=r"(r2), "=r"(r3) : "r"(addr));
}
__device__ __forceinline__ void mma16816(float& d0, float& d1, float& d2, float& d3,
                                         uint32_t a0, uint32_t a1, uint32_t a2, uint32_t a3,
                                         uint32_t b0, uint32_t b1) {
    asm volatile(
        "mma.sync.aligned.m16n8k16.row.col.f32.bf16.bf16.f32 "
        "{%0,%1,%2,%3}, {%4,%5,%6,%7}, {%8,%9}, {%0,%1,%2,%3};"
        : "+f"(d0), "+f"(d1), "+f"(d2), "+f"(d3)
        : "r"(a0), "r"(a1), "r"(a2), "r"(a3), "r"(b0), "r"(b1));
}

// ===========================================================================
// fused split-precision GEMM:  C[M,N] = A[M,K] * B[N,K]^T (fp32 via bf16)
//   per k-chunk computes Ah*Bh + Al*Bh + Ah*Bl from one staging.
//   mode 0: epilogue silu -> split into (OutH, OutL) bf16
//   mode 1: epilogue raw fp32 -> OutF
// 8 warps as 4 (rows, 32 each) x 2 (cols, 32 each).
// ===========================================================================
__global__ void __launch_bounds__(GTHREADS, 2)
gemm_bf16x3(const __nv_bfloat16* __restrict__ Ah,
            const __nv_bfloat16* __restrict__ Al,
            const __nv_bfloat16* __restrict__ Bh,
            const __nv_bfloat16* __restrict__ Bl,
            __nv_bfloat16* __restrict__ OutH,
            __nv_bfloat16* __restrict__ OutL,
            float* __restrict__ OutF,
            int mode) {
    extern __shared__ char dynsm[];
    const uint32_t sm_base = smem_u32(dynsm);

    const int tid    = threadIdx.x;
    const int wid    = tid >> 5;
    const int lane   = tid & 31;
    const int warp_m = wid & 3;    // 4 row-warps: 32 rows each
    const int warp_n = wid >> 2;   // 2 col-warps: 32 cols each
    const int bm = blockIdx.y * TILE_M;
    const int bn = blockIdx.x * TILE_N;

    // fp32 accumulators: 2 m16-tiles x 4 n8-tiles x 4 regs = 32
    float acc[2][4][4];
#pragma unroll
    for (int i = 0; i < 2; i++)
#pragma unroll
        for (int j = 0; j < 4; j++)
#pragma unroll
            for (int r = 0; r < 4; r++) acc[i][j][r] = 0.f;

    // ldmatrix per-lane byte offsets (before k16 advance + swizzle)
    uint32_t a_off[2], b_off[2];
#pragma unroll
    for (int mi = 0; mi < 2; mi++) {
        const int row = warp_m * 32 + mi * 16 + (lane & 15);
        a_off[mi] = row * 128 + (lane >> 4) * 16;
    }
#pragma unroll
    for (int g = 0; g < 2; g++) {
        const int row = warp_n * 32 + g * 16 + (lane & 15);
        b_off[g] = row * 128 + (lane >> 4) * 16;
    }

    // cp.async: Ah/Al 1024 vectors each, Bh/Bl 512 each; 12 per thread
    auto issue_chunk = [&](int c) {
        const int k0 = c * KCH;
        const uint32_t stage = sm_base + (uint32_t)(c % STAGES) * STAGE_BYTES;
        const __nv_bfloat16* Asrcs[2] = { Ah + (size_t)bm * DIM + k0,
                                          Al + (size_t)bm * DIM + k0 };
        const __nv_bfloat16* Bsrcs[2] = { Bh + (size_t)bn * DIM + k0,
                                          Bl + (size_t)bn * DIM + k0 };
#pragma unroll
        for (int t = 0; t < 2; t++) {      // A tiles: 1024 vectors each
#pragma unroll
            for (int i = 0; i < 4; i++) {
                const int f = tid + i * 256;
                const int r = f >> 3, v = f & 7;
                cp_async16(stage + (uint32_t)t * A_BYTES + SWZ128(r * 128 + v * 16),
                           Asrcs[t] + (size_t)r * DIM + v * 8);
            }
        }
#pragma unroll
        for (int t = 0; t < 2; t++) {      // B tiles: 512 vectors each
#pragma unroll
            for (int i = 0; i < 2; i++) {
                const int f = tid + i * 256;
                const int r = f >> 3, v = f & 7;
                cp_async16(stage + 2 * A_BYTES + (uint32_t)t * B_BYTES
                               + SWZ128(r * 128 + v * 16),
                           Bsrcs[t] + (size_t)r * DIM + v * 8);
            }
        }
    };

    // prologue: chunk 0
    issue_chunk(0);
    cp_commit();

    for (int c = 0; c < NCHUNK; c++) {
        cp_wait<0>();            // chunk c complete (this thread)
        __syncthreads();         // publish all copies; compute(c-1) fully done

        // overlap next chunk's global loads with this chunk's compute
        const int nc = c + 1;
        if (nc < NCHUNK) issue_chunk(nc);
        cp_commit();             // one group per iteration (possibly empty)

        const uint32_t sAh = sm_base + (uint32_t)(c % STAGES) * STAGE_BYTES;
        const uint32_t sAl = sAh + A_BYTES;
        const uint32_t sBh = sAh + 2 * A_BYTES;
        const uint32_t sBl = sBh + B_BYTES;
#pragma unroll
        for (int k16 = 0; k16 < 4; k16++) {
            const uint32_t kb = k16 * 32;
            uint32_t ah[2][4], al[2][4], bh[2][4], bl[2][4];
#pragma unroll
            for (int mi = 0; mi < 2; mi++) {
                ldmatrix_x4(ah[mi][0], ah[mi][1], ah[mi][2], ah[mi][3],
                            sAh + SWZ128(a_off[mi] + kb));
                ldmatrix_x4(al[mi][0], al[mi][1], al[mi][2], al[mi][3],
                            sAl + SWZ128(a_off[mi] + kb));
            }
#pragma unroll
            for (int g = 0; g < 2; g++) {
                ldmatrix_x4(bh[g][0], bh[g][1], bh[g][2], bh[g][3],
                            sBh + SWZ128(b_off[g] + kb));
                ldmatrix_x4(bl[g][0], bl[g][1], bl[g][2], bl[g][3],
                            sBl + SWZ128(b_off[g] + kb));
            }
            // Term sequence hoisted above the g-loop (within mi): each
            // accumulator's updates stay in order hh -> lh -> hl (bit-
            // identical), but same-accumulator MMA distance rises 2 -> 4.
#pragma unroll
            for (int mi = 0; mi < 2; mi++) {
                // term 1: Ah*Bh  (g = 0, 1)
#pragma unroll
                for (int g = 0; g < 2; g++) {
                    mma16816(acc[mi][2*g][0], acc[mi][2*g][1],
                             acc[mi][2*g][2], acc[mi][2*g][3],
                             ah[mi][0], ah[mi][1], ah[mi][2], ah[mi][3],
                             bh[g][0], bh[g][2]);
                    mma16816(acc[mi][2*g+1][0], acc[mi][2*g+1][1],
                             acc[mi][2*g+1][2], acc[mi][2*g+1][3],
                             ah[mi][0], ah[mi][1], ah[mi][2], ah[mi][3],
                             bh[g][1], bh[g][3]);
                }
                // term 2: Al*Bh  (g = 0, 1)
#pragma unroll
                for (int g = 0; g < 2; g++) {
                    mma16816(acc[mi][2*g][0], acc[mi][2*g][1],
                             acc[mi][2*g][2], acc[mi][2*g][3],
                             al[mi][0], al[mi][1], al[mi][2], al[mi][3],
                             bh[g][0], bh[g][2]);
                    mma16816(acc[mi][2*g+1][0], acc[mi][2*g+1][1],
                             acc[mi][2*g+1][2], acc[mi][2*g+1][3],
                             al[mi][0], al[mi][1], al[mi][2], al[mi][3],
                             bh[g][1], bh[g][3]);
                }
                // term 3: Ah*Bl  (g = 0, 1)
#pragma unroll
                for (int g = 0; g < 2; g++) {
                    mma16816(acc[mi][2*g][0], acc[mi][2*g][1],
                             acc[mi][2*g][2], acc[mi][2*g][3],
                             ah[mi][0], ah[mi][1], ah[mi][2], ah[mi][3],
                             bl[g][0], bl[g][2]);
                    mma16816(acc[mi][2*g+1][0], acc[mi][2*g+1][1],
                             acc[mi][2*g+1][2], acc[mi][2*g+1][3],
                             ah[mi][0], ah[mi][1], ah[mi][2], ah[mi][3],
                             bl[g][1], bl[g][3]);
                }
            }
        }
    }

    // ---- epilogue ----
#pragma unroll
    for (int mi = 0; mi < 2; mi++) {
        const int row0 = bm + warp_m * 32 + mi * 16 + (lane >> 2);
#pragma unroll
        for (int ni = 0; ni < 4; ni++) {
            const int col = bn + warp_n * 32 + ni * 8 + (lane & 3) * 2;
#pragma unroll
            for (int half = 0; half < 2; half++) {
                const int row = row0 + half * 8;
                const size_t idx = (size_t)row * DIM + col;
                float v0 = acc[mi][ni][half * 2 + 0];
                float v1 = acc[mi][ni][half * 2 + 1];
                if (mode == 0) {
                    v0 = v0 / (1.f + expf(-v0));
                    v1 = v1 / (1.f + expf(-v1));
                    __nv_bfloat16 h0 = __float2bfloat16(v0);
                    __nv_bfloat16 h1 = __float2bfloat16(v1);
                    __nv_bfloat16 l0 = __float2bfloat16(v0 - __bfloat162float(h0));
                    __nv_bfloat16 l1 = __float2bfloat16(v1 - __bfloat162float(h1));
                    *(__nv_bfloat162*)(OutH + idx) = __halves2bfloat162(h0, h1);
                    *(__nv_bfloat162*)(OutL + idx) = __halves2bfloat162(l0, l1);
                } else {
                    *(float2*)(OutF + idx) = make_float2(v0, v1);
                }
            }
        }
    }
}

// ===========================================================================
// fp32 -> (hi, lo) bf16 split; 4 tensors in ONE launch (keeps gemm3 at ncu's
// -s 5 slot). Segments: [0,n0) x, [n0,n0+n1) w1, then w3, w2.
// ===========================================================================
__global__ void split4_kernel(const float4* __restrict__ i0, __nv_bfloat162* __restrict__ h0, __nv_bfloat162* __restrict__ l0, int n0,
                              const float4* __restrict__ i1, __nv_bfloat162* __restrict__ h1, __nv_bfloat162* __restrict__ l1, int n1,
                              const float4* __restrict__ i2, __nv_bfloat162* __restrict__ h2, __nv_bfloat162* __restrict__ l2, int n2,
                              const float4* __restrict__ i3, __nv_bfloat162* __restrict__ h3, __nv_bfloat162* __restrict__ l3, int n3) {
    const int total = n0 + n1 + n2 + n3;
    int i = blockIdx.x * blockDim.x + threadIdx.x;
    const int stride = gridDim.x * blockDim.x;
    for (; i < total; i += stride) {
        const float4* in; __nv_bfloat162* hi; __nv_bfloat162* lo; int j = i;
        if (j < n0)                { in = i0; hi = h0; lo = l0; }
        else if ((j -= n0) < n1)   { in = i1; hi = h1; lo = l1; }
        else if ((j -= n1) < n2)   { in = i2; hi = h2; lo = l2; }
        else { j -= n2;              in = i3; hi = h3; lo = l3; }
        float4 v = in[j];
        __nv_bfloat16 a0 = __float2bfloat16(v.x), a1 = __float2bfloat16(v.y);
        __nv_bfloat16 a2 = __float2bfloat16(v.z), a3 = __float2bfloat16(v.w);
        __nv_bfloat16 b0 = __float2bfloat16(v.x - __bfloat162float(a0));
        __nv_bfloat16 b1 = __float2bfloat16(v.y - __bfloat162float(a1));
        __nv_bfloat16 b2 = __float2bfloat16(v.z - __bfloat162float(a2));
        __nv_bfloat16 b3 = __float2bfloat16(v.w - __bfloat162float(a3));
        hi[2 * j]     = __halves2bfloat162(a0, a1);
        hi[2 * j + 1] = __halves2bfloat162(a2, a3);
        lo[2 * j]     = __halves2bfloat162(b0, b1);
        lo[2 * j + 1] = __halves2bfloat162(b2, b3);
    }
}

// ===========================================================================
// zero-fill output
// ===========================================================================
__global__ void zero_kernel(float4* __restrict__ out, size_t n4) {
    size_t i = (size_t)blockIdx.x * blockDim.x + threadIdx.x;
    size_t stride = (size_t)gridDim.x * blockDim.x;
    float4 z = make_float4(0.f, 0.f, 0.f, 0.f);
    for (; i < n4; i += stride) out[i] = z;
}

// ===========================================================================
// routing: one warp per token; softmax -> top2 -> normalized gates
// ===========================================================================
__global__ void routing_kernel(const float* __restrict__ x,
                               const float* __restrict__ wr,
                               float* __restrict__ C) {
    int gwarp = (blockIdx.x * blockDim.x + threadIdx.x) >> 5;
    int lane  = threadIdx.x & 31;
    if (gwarp >= NTOK) return;
    const float* xr = x + (size_t)gwarp * DIM;
    float acc[NEXP];
#pragma unroll
    for (int e = 0; e < NEXP; e++) acc[e] = 0.f;
    for (int k = lane; k < DIM; k += 32) {
        float xv = xr[k];
#pragma unroll
        for (int e = 0; e < NEXP; e++)
            acc[e] = fmaf(xv, wr[e * DIM + k], acc[e]);
    }
#pragma unroll
    for (int e = 0; e < NEXP; e++) {
#pragma unroll
        for (int off = 16; off > 0; off >>= 1)
            acc[e] += __shfl_xor_sync(0xffffffffu, acc[e], off);
    }
    if (lane == 0) {
        float m = acc[0];
#pragma unroll
        for (int e = 1; e < NEXP; e++) m = fmaxf(m, acc[e]);
        float p[NEXP];
#pragma unroll
        for (int e = 0; e < NEXP; e++) p[e] = expf(acc[e] - m);
        int e0 = 0; float p0 = p[0];
#pragma unroll
        for (int e = 1; e < NEXP; e++) if (p[e] > p0) { p0 = p[e]; e0 = e; }
        int e1 = -1; float p1 = -1.f;
#pragma unroll
        for (int e = 0; e < NEXP; e++)
            if (e != e0 && p[e] > p1) { p1 = p[e]; e1 = e; }
        float inv = 1.f / (p0 + p1);
        float* Cn = C + (size_t)gwarp * NEXP;
#pragma unroll
        for (int e = 0; e < NEXP; e++) {
            float v = 0.f;
            if (e == e0) v = p0 * inv;
            else if (e == e1) v = p1 * inv;
            Cn[e] = v;
        }
    }
}

// ===========================================================================
// expert-weighted reduction (two-stage, deterministic)
// ===========================================================================
__global__ void reduce_partial_kernel(const float* __restrict__ h,
                                      const float* __restrict__ C,
                                      float* __restrict__ part) {
    const int col = blockIdx.x * 128 + threadIdx.x;
    const int n0 = blockIdx.y * 128;
    float acc[NEXP];
#pragma unroll
    for (int e = 0; e < NEXP; e++) acc[e] = 0.f;
    for (int i = 0; i < 128; i++) {
        const int n = n0 + i;
        const float hv = h[(size_t)n * DIM + col];
        const float* Cn = C + (size_t)n * NEXP;
#pragma unroll
        for (int e = 0; e < NEXP; e++)
            acc[e] = fmaf(hv, Cn[e], acc[e]);
    }
#pragma unroll
    for (int e = 0; e < NEXP; e++)
        part[((size_t)blockIdx.y * NEXP + e) * DIM + col] = acc[e];
}

__global__ void reduce_final_kernel(const float* __restrict__ part,
                                    float* __restrict__ out) {
    const int id = blockIdx.x * blockDim.x + threadIdx.x;
    if (id >= NEXP * DIM) return;
    const int e = id / DIM;
    const int col = id % DIM;
    float s = 0.f;
#pragma unroll 4
    for (int by = 0; by < NTOK / 128; by++)
        s += part[((size_t)by * NEXP + e) * DIM + col];
    out[(size_t)e * DIM + col] = s;
}

// ===========================================================================
extern "C" void kernel_launch(void* const* d_in, const int* in_sizes, int n_in,
                              void* d_out, int out_size) {
    const float* x  = (const float*)d_in[0];
    const float* w1 = (const float*)d_in[1];
    const float* w3 = (const float*)d_in[2];
    const float* w2 = (const float*)d_in[3];
    const float* wr = (const float*)d_in[4];
    float* out = (float*)d_out;

    __nv_bfloat16 *xh, *xl, *t1h, *t1l, *w1h, *w1l, *w3h, *w3l, *w2h, *w2l;
    float *hbuf, *C, *part;
    cudaGetSymbolAddress((void**)&xh,  g_xh);
    cudaGetSymbolAddress((void**)&xl,  g_xl);
    cudaGetSymbolAddress((void**)&t1h, g_t1h);
    cudaGetSymbolAddress((void**)&t1l, g_t1l);
    cudaGetSymbolAddress((void**)&w1h, g_w1h);
    cudaGetSymbolAddress((void**)&w1l, g_w1l);
    cudaGetSymbolAddress((void**)&w3h, g_w3h);
    cudaGetSymbolAddress((void**)&w3l, g_w3l);
    cudaGetSymbolAddress((void**)&w2h, g_w2h);
    cudaGetSymbolAddress((void**)&w2l, g_w2l);
    cudaGetSymbolAddress((void**)&hbuf, g_h);
    cudaGetSymbolAddress((void**)&C,    g_C);
    cudaGetSymbolAddress((void**)&part, g_part);

    cudaFuncSetAttribute(gemm_bf16x3,
                         cudaFuncAttributeMaxDynamicSharedMemorySize,
                         GEMM_DYN_SMEM);

    // launch 1: zero output (harness poisons it)
    {
        size_t n4 = (size_t)out_size / 4;
        int blocks = (int)((n4 + 255) / 256);
        if (blocks > 16384) blocks = 16384;
        zero_kernel<<<blocks, 256>>>((float4*)out, n4);
    }

    // launch 2: routing coefficients (fp32, faithful top-k)
    routing_kernel<<<(NTOK * 32) / 256, 256>>>(x, wr, C);

    // launch 3: all hi/lo splits fused
    const int nx4 = NTOK * DIM / 4, nw4 = DIM * DIM / 4;
    split4_kernel<<<2048, 256>>>(
        (const float4*)x,  (__nv_bfloat162*)xh,  (__nv_bfloat162*)xl,  nx4,
        (const float4*)w1, (__nv_bfloat162*)w1h, (__nv_bfloat162*)w1l, nw4,
        (const float4*)w3, (__nv_bfloat162*)w3h, (__nv_bfloat162*)w3l, nw4,
        (const float4*)w2, (__nv_bfloat162*)w2h, (__nv_bfloat162*)w2l, nw4);

    // launches 4-6: FFN chain (ncu -s 5 -c 1 profiles launch 6 = gemm3)
    dim3 ggrid(DIM / TILE_N, NTOK / TILE_M);  // (32, 64)
    gemm_bf16x3<<<ggrid, GTHREADS, GEMM_DYN_SMEM>>>(xh, xl, w1h, w1l,
                                                    t1h, t1l, nullptr, 0);
    gemm_bf16x3<<<ggrid, GTHREADS, GEMM_DYN_SMEM>>>(t1h, t1l, w3h, w3l,
                                                    xh, xl, nullptr, 0);   // reuse x bufs
    gemm_bf16x3<<<ggrid, GTHREADS, GEMM_DYN_SMEM>>>(xh, xl, w2h, w2l,
                                                    nullptr, nullptr, hbuf, 1);

    // launches 7-8: expert-weighted reduction into rows 0..7
    reduce_partial_kernel<<<dim3(DIM / 128, NTOK / 128), 128>>>(hbuf, C, part);
    reduce_final_kernel<<<(NEXP * DIM + 255) / 256, 256>>>(part, out);
}